// round 8
// baseline (speedup 1.0000x reference)
#include <cuda_runtime.h>

#define NC 4096
#define NA 2048
#define NB (NC + NA)          // 6144 bodies
#define TPB 128
#define IPT 2                 // i-bodies per thread
#define ITILE (TPB * IPT)     // 256 i per block
#define ITILES (NB / ITILE)   // 24 i-tiles  (tiles 0..15 circle, 16..23 aabb)
#define CHUNK 256             // j-chunk size
#define NCY (NC / CHUNK)      // 16 circle j-chunks
#define NAY (NA / CHUNK)      // 8 aabb j-chunks
#define NJY (NCY + NAY)       // 24 j-chunks
#define EPSF 1e-9f

// partial corrections: [NJY][NB] float2
__device__ float2 g_partial[NJY * NB];
__device__ int    g_cnt[ITILES] = {};

typedef unsigned long long u64;

__device__ __forceinline__ float rsq_approx(float x) {
    float r;
    asm("rsqrt.approx.f32 %0, %1;" : "=f"(r) : "f"(x));
    return r;
}
__device__ __forceinline__ u64 pack2(float lo, float hi) {
    u64 r; asm("mov.b64 %0, {%1, %2};" : "=l"(r) : "f"(lo), "f"(hi)); return r;
}
__device__ __forceinline__ void unpack2(u64 v, float& lo, float& hi) {
    asm("mov.b64 {%0, %1}, %2;" : "=f"(lo), "=f"(hi) : "l"(v));
}
__device__ __forceinline__ u64 add2(u64 a, u64 b) {
    u64 r; asm("add.rn.f32x2 %0, %1, %2;" : "=l"(r) : "l"(a), "l"(b)); return r;
}
__device__ __forceinline__ u64 fma2(u64 a, u64 b, u64 c) {
    u64 r; asm("fma.rn.f32x2 %0, %1, %2, %3;" : "=l"(r) : "l"(a), "l"(b), "l"(c)); return r;
}

__global__ void __launch_bounds__(TPB)
collide_kernel(const float* __restrict__ cpos, const float* __restrict__ crad,
               const float* __restrict__ apos, const float* __restrict__ ahalf,
               float* __restrict__ out)
{
    // one float4 per j-body: circle (−x, −y, 0.5*r, 0) ; aabb (−x, −y, hx, hy)
    __shared__ float4 sj[CHUNK];
    __shared__ int s_old;

    const int tid = threadIdx.x;
    const int bx  = blockIdx.x;                   // i-tile
    const int i0  = bx * ITILE + tid;             // first i-body
    const int i1  = i0 + TPB;                     // second i-body (same type)
    const bool i_is_circle = (bx < NC / ITILE);
    const int jy = blockIdx.y;
    const bool j_is_circle = (jy < NCY);
    const int j0 = j_is_circle ? (jy * CHUNK) : ((jy - NCY) * CHUNK);

    // stage CHUNK j-bodies (2 per thread), positions negated
    #pragma unroll
    for (int t = tid; t < CHUNK; t += TPB) {
        if (j_is_circle) {
            float2 p = ((const float2*)cpos)[j0 + t];
            sj[t] = make_float4(-p.x, -p.y, 0.5f * crad[j0 + t], 0.0f);
        } else {
            float2 p = ((const float2*)apos)[j0 + t];
            float2 h = ((const float2*)ahalf)[j0 + t];
            sj[t] = make_float4(-p.x, -p.y, h.x, h.y);
        }
    }

    // hoisted i-state for both bodies
    float ra0, rb0, ra1, rb1;    // circle: ra=0.5*r ; aabb: ra=hx, rb=hy
    u64 pixy0, pixy1;
    int ia0 = 0, ia1 = 0;
    if (i_is_circle) {
        float2 p0 = ((const float2*)cpos)[i0];
        float2 p1 = ((const float2*)cpos)[i1];
        pixy0 = pack2(p0.x, p0.y);
        pixy1 = pack2(p1.x, p1.y);
        ra0 = 0.5f * crad[i0]; rb0 = 0.0f;
        ra1 = 0.5f * crad[i1]; rb1 = 0.0f;
    } else {
        ia0 = i0 - NC; ia1 = i1 - NC;
        float2 p0 = ((const float2*)apos)[ia0];
        float2 p1 = ((const float2*)apos)[ia1];
        float2 h0 = ((const float2*)ahalf)[ia0];
        float2 h1 = ((const float2*)ahalf)[ia1];
        pixy0 = pack2(p0.x, p0.y);
        pixy1 = pack2(p1.x, p1.y);
        ra0 = h0.x; rb0 = h0.y;
        ra1 = h1.x; rb1 = h1.y;
    }

    __syncthreads();

    u64 acc0 = pack2(0.0f, 0.0f);
    u64 acc1 = pack2(0.0f, 0.0f);

    if (i_is_circle) {
        if (j_is_circle) {
            // circle vs circle. EPS clamp => self-pair d=(+0,+0) contributes exactly 0.
            #pragma unroll 8
            for (int k = 0; k < CHUNK; k++) {
                float4 b = sj[k];
                u64 bxy = pack2(b.x, b.y);
                u64 d0 = add2(pixy0, bxy);
                u64 d1 = add2(pixy1, bxy);
                float dx0, dy0; unpack2(d0, dx0, dy0);
                float dx1, dy1; unpack2(d1, dx1, dy1);
                float d20 = fmaxf(fmaf(dx0, dx0, dy0 * dy0), EPSF);
                float d21 = fmaxf(fmaf(dx1, dx1, dy1 * dy1), EPSF);
                float inv0 = rsq_approx(d20);
                float inv1 = rsq_approx(d21);
                float s0 = fmaxf(fmaf(ra0 + b.z, inv0, -0.5f), 0.0f);
                float s1 = fmaxf(fmaf(ra1 + b.z, inv1, -0.5f), 0.0f);
                acc0 = fma2(pack2(s0, s0), d0, acc0);
                acc1 = fma2(pack2(s1, s1), d1, acc1);
            }
        } else {
            // circle vs aabb (push on circle)
            #pragma unroll 8
            for (int k = 0; k < CHUNK; k++) {
                float4 b = sj[k];
                u64 bxy = pack2(b.x, b.y);
                u64 r0 = add2(pixy0, bxy);
                u64 r1 = add2(pixy1, bxy);
                float rx0, ry0; unpack2(r0, rx0, ry0);
                float rx1, ry1; unpack2(r1, rx1, ry1);
                float dx0 = rx0 - fminf(fmaxf(rx0, -b.z), b.z);
                float dy0 = ry0 - fminf(fmaxf(ry0, -b.w), b.w);
                float dx1 = rx1 - fminf(fmaxf(rx1, -b.z), b.z);
                float dy1 = ry1 - fminf(fmaxf(ry1, -b.w), b.w);
                float dd20 = fmaxf(fmaf(dx0, dx0, dy0 * dy0), EPSF);
                float dd21 = fmaxf(fmaf(dx1, dx1, dy1 * dy1), EPSF);
                float inv0 = rsq_approx(dd20);
                float inv1 = rsq_approx(dd21);
                float s0 = fmaxf(fmaf(ra0, inv0, -0.5f), 0.0f);
                float s1 = fmaxf(fmaf(ra1, inv1, -0.5f), 0.0f);
                acc0 = fma2(pack2(s0, s0), pack2(dx0, dy0), acc0);
                acc1 = fma2(pack2(s1, s1), pack2(dx1, dy1), acc1);
            }
        }
    } else {
        if (j_is_circle) {
            // aabb vs circle: rel' = ai - cj = -rel => box push = +s*diff'
            #pragma unroll 8
            for (int k = 0; k < CHUNK; k++) {
                float4 b = sj[k];
                u64 bxy = pack2(b.x, b.y);
                u64 r0 = add2(pixy0, bxy);
                u64 r1 = add2(pixy1, bxy);
                float rx0, ry0; unpack2(r0, rx0, ry0);
                float rx1, ry1; unpack2(r1, rx1, ry1);
                float dx0 = rx0 - fminf(fmaxf(rx0, -ra0), ra0);
                float dy0 = ry0 - fminf(fmaxf(ry0, -rb0), rb0);
                float dx1 = rx1 - fminf(fmaxf(rx1, -ra1), ra1);
                float dy1 = ry1 - fminf(fmaxf(ry1, -rb1), rb1);
                float dd20 = fmaxf(fmaf(dx0, dx0, dy0 * dy0), EPSF);
                float dd21 = fmaxf(fmaf(dx1, dx1, dy1 * dy1), EPSF);
                float inv0 = rsq_approx(dd20);
                float inv1 = rsq_approx(dd21);
                float s0 = fmaxf(fmaf(b.z, inv0, -0.5f), 0.0f);   // b.z = 0.5*rj
                float s1 = fmaxf(fmaf(b.z, inv1, -0.5f), 0.0f);
                acc0 = fma2(pack2(s0, s0), pack2(dx0, dy0), acc0);
                acc1 = fma2(pack2(s1, s1), pack2(dx1, dy1), acc1);
            }
        } else {
            // aabb vs aabb
            float cx0 = 0.0f, cy0 = 0.0f, cx1 = 0.0f, cy1 = 0.0f;
            #pragma unroll 8
            for (int k = 0; k < CHUNK; k++) {
                float4 b = sj[k];
                u64 bxy = pack2(b.x, b.y);
                int j = j0 + k;
                u64 d0 = add2(pixy0, bxy);
                u64 d1 = add2(pixy1, bxy);
                float dax0, day0; unpack2(d0, dax0, day0);
                float dax1, day1; unpack2(d1, dax1, day1);
                float ovx0 = (ra0 + b.z) - fabsf(dax0);
                float ovy0 = (rb0 + b.w) - fabsf(day0);
                float ovx1 = (ra1 + b.z) - fabsf(dax1);
                float ovy1 = (rb1 + b.w) - fabsf(day1);
                bool hit0 = (ovx0 > 0.0f) && (ovy0 > 0.0f) && (ia0 != j);
                bool hit1 = (ovx1 > 0.0f) && (ovy1 > 0.0f) && (ia1 != j);
                bool ux0 = (ovx0 <= ovy0);
                bool ux1 = (ovx1 <= ovy1);
                cx0 += (hit0 && ux0)  ? copysignf(0.5f * ovx0, dax0) : 0.0f;
                cy0 += (hit0 && !ux0) ? copysignf(0.5f * ovy0, day0) : 0.0f;
                cx1 += (hit1 && ux1)  ? copysignf(0.5f * ovx1, dax1) : 0.0f;
                cy1 += (hit1 && !ux1) ? copysignf(0.5f * ovy1, day1) : 0.0f;
            }
            acc0 = pack2(cx0, cy0);
            acc1 = pack2(cx1, cy1);
        }
    }

    {
        float ax, ay;
        unpack2(acc0, ax, ay);
        g_partial[(size_t)jy * NB + i0] = make_float2(ax, ay);
        unpack2(acc1, ax, ay);
        g_partial[(size_t)jy * NB + i1] = make_float2(ax, ay);
    }

    // ---- last-arriving block of this i-tile folds all partials (fixed order) ----
    __threadfence();                       // release partial writes
    if (tid == 0) s_old = atomicAdd(&g_cnt[bx], 1);
    __syncthreads();
    if (s_old == NJY - 1) {
        __threadfence();                   // see all partials
        #pragma unroll
        for (int v = 0; v < IPT; v++) {
            int i = (v == 0) ? i0 : i1;
            float2 base = i_is_circle ? ((const float2*)cpos)[i]
                                      : ((const float2*)apos)[i - NC];
            float sx = base.x, sy = base.y;
            #pragma unroll
            for (int y = 0; y < NJY; y++) {    // fixed order => deterministic
                float2 p = g_partial[(size_t)y * NB + i];
                sx += p.x; sy += p.y;
            }
            ((float2*)out)[i] = make_float2(sx, sy);
        }
        if (tid == 0) g_cnt[bx] = 0;       // reset for next graph replay
    }
}

extern "C" void kernel_launch(void* const* d_in, const int* in_sizes, int n_in,
                              void* d_out, int out_size)
{
    const float* cpos  = (const float*)d_in[0];   // [4096,2]
    const float* crad  = (const float*)d_in[1];   // [4096]
    const float* apos  = (const float*)d_in[2];   // [2048,2]
    const float* ahalf = (const float*)d_in[3];   // [2048,2]
    float* out = (float*)d_out;                   // [6144,2]

    dim3 grid(ITILES, NJY);
    collide_kernel<<<grid, TPB>>>(cpos, crad, apos, ahalf, out);
}

// round 9
// speedup vs baseline: 1.0467x; 1.0467x over previous
#include <cuda_runtime.h>

#define NC 4096
#define NA 2048
#define NB (NC + NA)          // 6144 bodies
#define TPB 128
#define ITILES (NB / TPB)     // 48 i-tiles (0..31 circle, 32..47 aabb)
#define CHUNK 128             // j-chunk size
#define NCY (NC / CHUNK)      // 32 circle j-chunks
#define NAY (NA / CHUNK)      // 16 aabb j-chunks
#define NJY (NCY + NAY)       // 48 j-chunks
#define EPSF 1e-9f

// partial corrections: [NJY][NB] float2
__device__ float2 g_partial[NJY * NB];
__device__ int    g_cnt[ITILES] = {};

typedef unsigned long long u64;

__device__ __forceinline__ float rsq_approx(float x) {
    float r;
    asm("rsqrt.approx.f32 %0, %1;" : "=f"(r) : "f"(x));
    return r;
}
__device__ __forceinline__ u64 pack2(float lo, float hi) {
    u64 r; asm("mov.b64 %0, {%1, %2};" : "=l"(r) : "f"(lo), "f"(hi)); return r;
}
__device__ __forceinline__ void unpack2(u64 v, float& lo, float& hi) {
    asm("mov.b64 {%0, %1}, %2;" : "=f"(lo), "=f"(hi) : "l"(v));
}
__device__ __forceinline__ u64 add2(u64 a, u64 b) {
    u64 r; asm("add.rn.f32x2 %0, %1, %2;" : "=l"(r) : "l"(a), "l"(b)); return r;
}
__device__ __forceinline__ u64 fma2(u64 a, u64 b, u64 c) {
    u64 r; asm("fma.rn.f32x2 %0, %1, %2, %3;" : "=l"(r) : "l"(a), "l"(b), "l"(c)); return r;
}

__global__ void __launch_bounds__(TPB)
collide_kernel(const float* __restrict__ cpos, const float* __restrict__ crad,
               const float* __restrict__ apos, const float* __restrict__ ahalf,
               float* __restrict__ out)
{
    // one float4 per j-body: circle (−x, −y, 0.5*r, 0) ; aabb (−x, −y, hx, hy)
    __shared__ float4 sj[CHUNK];
    __shared__ int s_old;

    const int tid = threadIdx.x;
    const int bx  = blockIdx.x;                 // i-tile
    const int i   = bx * TPB + tid;             // body index 0..NB-1
    const bool i_is_circle = (i < NC);
    const int jy = blockIdx.y;
    const bool j_is_circle = (jy < NCY);
    const int j0 = j_is_circle ? (jy * CHUNK) : ((jy - NCY) * CHUNK);

    // stage CHUNK j-bodies (one per thread), positions negated
    {
        const int t = tid;
        if (j_is_circle) {
            float2 p = ((const float2*)cpos)[j0 + t];
            sj[t] = make_float4(-p.x, -p.y, 0.5f * crad[j0 + t], 0.0f);
        } else {
            float2 p = ((const float2*)apos)[j0 + t];
            float2 h = ((const float2*)ahalf)[j0 + t];
            sj[t] = make_float4(-p.x, -p.y, h.x, h.y);
        }
    }

    // hoisted i-state
    float pix, piy, ra, rb;      // circle: ra=0.5*r ; aabb: ra=hx, rb=hy
    int ia = 0;
    if (i_is_circle) {
        float2 p = ((const float2*)cpos)[i];
        pix = p.x; piy = p.y;
        ra = 0.5f * crad[i]; rb = 0.0f;
    } else {
        ia = i - NC;
        float2 p = ((const float2*)apos)[ia];
        float2 h = ((const float2*)ahalf)[ia];
        pix = p.x; piy = p.y;
        ra = h.x; rb = h.y;
    }
    const u64 pixy = pack2(pix, piy);

    __syncthreads();

    u64 acc = pack2(0.0f, 0.0f);

    if (i_is_circle) {
        if (j_is_circle) {
            // circle vs circle. EPS clamp => self-pair d=(+0,+0) contributes exactly 0.
            #pragma unroll 8
            for (int k = 0; k < CHUNK; k++) {
                float4 b = sj[k];
                u64 d = add2(pixy, pack2(b.x, b.y));    // (dx,dy) = pi - pj
                float dx, dy; unpack2(d, dx, dy);
                float d2 = fmaxf(fmaf(dx, dx, dy * dy), EPSF);
                float inv = rsq_approx(d2);
                float s = fmaxf(fmaf(ra + b.z, inv, -0.5f), 0.0f);
                acc = fma2(pack2(s, s), d, acc);
            }
        } else {
            // circle vs aabb (push on circle)
            #pragma unroll 8
            for (int k = 0; k < CHUNK; k++) {
                float4 b = sj[k];
                u64 rel = add2(pixy, pack2(b.x, b.y));  // ci - aj
                float rx, ry; unpack2(rel, rx, ry);
                float dx = rx - fminf(fmaxf(rx, -b.z), b.z);
                float dy = ry - fminf(fmaxf(ry, -b.w), b.w);
                float dd2 = fmaxf(fmaf(dx, dx, dy * dy), EPSF);
                float inv = rsq_approx(dd2);
                float s = fmaxf(fmaf(ra, inv, -0.5f), 0.0f);   // ra = 0.5*ri
                acc = fma2(pack2(s, s), pack2(dx, dy), acc);
            }
        }
    } else {
        if (j_is_circle) {
            // aabb vs circle: rel' = ai - cj = -rel => box push = +s*diff'
            #pragma unroll 8
            for (int k = 0; k < CHUNK; k++) {
                float4 b = sj[k];
                u64 rel = add2(pixy, pack2(b.x, b.y));  // ai - cj
                float rx, ry; unpack2(rel, rx, ry);
                float dx = rx - fminf(fmaxf(rx, -ra), ra);   // ra=hx
                float dy = ry - fminf(fmaxf(ry, -rb), rb);   // rb=hy
                float dd2 = fmaxf(fmaf(dx, dx, dy * dy), EPSF);
                float inv = rsq_approx(dd2);
                float s = fmaxf(fmaf(b.z, inv, -0.5f), 0.0f);   // b.z = 0.5*rj
                acc = fma2(pack2(s, s), pack2(dx, dy), acc);
            }
        } else {
            // aabb vs aabb
            float cx = 0.0f, cy = 0.0f;
            #pragma unroll 8
            for (int k = 0; k < CHUNK; k++) {
                float4 b = sj[k];
                int j = j0 + k;
                u64 da = add2(pixy, pack2(b.x, b.y));   // ai - aj
                float dax, day; unpack2(da, dax, day);
                float ovx = (ra + b.z) - fabsf(dax);
                float ovy = (rb + b.w) - fabsf(day);
                bool hit = (ovx > 0.0f) && (ovy > 0.0f) && (ia != j);
                bool usex = (ovx <= ovy);
                cx += (hit && usex)  ? copysignf(0.5f * ovx, dax) : 0.0f;
                cy += (hit && !usex) ? copysignf(0.5f * ovy, day) : 0.0f;
            }
            acc = pack2(cx, cy);
        }
    }

    {
        float ax, ay; unpack2(acc, ax, ay);
        g_partial[(size_t)jy * NB + i] = make_float2(ax, ay);
    }

    // ---- last-arriving block of this i-tile folds all partials (fixed order) ----
    __threadfence();                       // release partial write
    if (tid == 0) s_old = atomicAdd(&g_cnt[bx], 1);
    __syncthreads();
    if (s_old == NJY - 1) {
        __threadfence();                   // see all partials
        float2 base = i_is_circle ? ((const float2*)cpos)[i]
                                  : ((const float2*)apos)[i - NC];
        float sx = base.x, sy = base.y;
        #pragma unroll
        for (int y = 0; y < NJY; y++) {    // fixed order => deterministic
            float2 p = g_partial[(size_t)y * NB + i];
            sx += p.x; sy += p.y;
        }
        ((float2*)out)[i] = make_float2(sx, sy);
        if (tid == 0) g_cnt[bx] = 0;       // reset for next graph replay
    }
}

extern "C" void kernel_launch(void* const* d_in, const int* in_sizes, int n_in,
                              void* d_out, int out_size)
{
    const float* cpos  = (const float*)d_in[0];   // [4096,2]
    const float* crad  = (const float*)d_in[1];   // [4096]
    const float* apos  = (const float*)d_in[2];   // [2048,2]
    const float* ahalf = (const float*)d_in[3];   // [2048,2]
    float* out = (float*)d_out;                   // [6144,2]

    dim3 grid(ITILES, NJY);
    collide_kernel<<<grid, TPB>>>(cpos, crad, apos, ahalf, out);
}